// round 10
// baseline (speedup 1.0000x reference)
#include <cuda_runtime.h>
#include <cuda_bf16.h>
#include <mma.h>
#include <cstdint>
#include <math.h>

using namespace nvcuda;

// ===========================================================================
// Threefry-2x32 (exact JAX)
// ===========================================================================
__host__ __device__ __forceinline__ void threefry2x32(
    unsigned k0, unsigned k1, unsigned x0, unsigned x1,
    unsigned &o0, unsigned &o1)
{
    const unsigned ks2 = k0 ^ k1 ^ 0x1BD11BDAu;
    unsigned a = x0 + k0, b = x1 + k1;
#define TF_ROT(v,d) (((v)<<(d))|((v)>>(32-(d))))
#define TF_R4(r0_,r1_,r2_,r3_) \
    a+=b; b=TF_ROT(b,r0_); b^=a; \
    a+=b; b=TF_ROT(b,r1_); b^=a; \
    a+=b; b=TF_ROT(b,r2_); b^=a; \
    a+=b; b=TF_ROT(b,r3_); b^=a;
    TF_R4(13,15,26, 6);  a+=k1;  b+=ks2+1u;
    TF_R4(17,29,16,24);  a+=ks2; b+=k0 +2u;
    TF_R4(13,15,26, 6);  a+=k0;  b+=k1 +3u;
    TF_R4(17,29,16,24);  a+=k1;  b+=ks2+4u;
    TF_R4(13,15,26, 6);  a+=ks2; b+=k0 +5u;
    o0 = a; o1 = b;
#undef TF_R4
#undef TF_ROT
}

// ===========================================================================
// FFMA2 helpers
// ===========================================================================
__device__ __forceinline__ unsigned long long pack_dup(float a) {
    unsigned long long r;
    asm("mov.b64 %0, {%1, %1};" : "=l"(r) : "f"(a));
    return r;
}
__device__ __forceinline__ unsigned long long fma2(
    unsigned long long a, unsigned long long b, unsigned long long c) {
    unsigned long long d;
    asm("fma.rn.f32x2 %0, %1, %2, %3;" : "=l"(d) : "l"(a), "l"(b), "l"(c));
    return d;
}

#define BARX(id) asm volatile("bar.sync %0, 256;" :: "r"(id) : "memory")

// ===========================================================================
// Static scratch: W transposed + split into 3 bf16 planes [3][E=128][D]
// ===========================================================================
#define MAX_D 4096
__device__ __nv_bfloat16 g_Ws[3u * 128u * MAX_D];

__global__ void wsplit_kernel(const float* __restrict__ W, int D)
{
    __shared__ float tile[32][33];
    const int d0 = blockIdx.x * 32, e0 = blockIdx.y * 32;
    const int tx = threadIdx.x, ty = threadIdx.y;
#pragma unroll
    for (int i = ty; i < 32; i += 8)
        tile[i][tx] = W[(size_t)(d0 + i) * 128 + e0 + tx];
    __syncthreads();
#pragma unroll
    for (int i = ty; i < 32; i += 8) {
        float a = tile[tx][i];
        __nv_bfloat16 b0 = __float2bfloat16(a);
        float r = a - __bfloat162float(b0);
        __nv_bfloat16 b1 = __float2bfloat16(r);
        float r2 = r - __bfloat162float(b1);
        __nv_bfloat16 b2 = __float2bfloat16(r2);
        size_t o = (size_t)(e0 + i) * D + d0 + tx;
        g_Ws[o]                      = b0;
        g_Ws[(size_t)128 * D + o]    = b1;
        g_Ws[(size_t)256 * D + o]    = b2;
    }
}

// ===========================================================================
// Hybrid GEMM: 512 threads/CTA, tile 128x128.
//   warps 0-7  (fp32/FFMA2 crew): rows [bm+64, bm+128), BK=16
//   warps 8-15 (HMMA bf16x6 crew): rows [bm, bm+64), CHUNK=32, RZ-flush
// ===========================================================================
#define FP_AS_LD    68
#define FP_AS_BYTES (16 * FP_AS_LD * 4)          // 4352
#define FP_BS_BYTES (16 * 128 * 4)               // 8192
#define FP_BYTES    (FP_AS_BYTES + FP_BS_BYTES)  // 12544 (128-aligned)

#define LDP         40
#define APL_B       (64  * LDP * 2)              // 5120
#define BPL_B       (128 * LDP * 2)              // 10240
#define HB_BUF      (3 * APL_B + 3 * BPL_B)      // 46080
#define SMEM_TOTAL  (FP_BYTES + 2 * HB_BUF)      // 104704

#define FLUSH_EVERY 4

__global__ __launch_bounds__(512, 1)
void gemm_hybrid(const float* __restrict__ H, const float* __restrict__ W,
                 float* __restrict__ out, int D)
{
    extern __shared__ char smem[];
    const int tid = threadIdx.x;
    const int bm  = blockIdx.x * 128;

    if (tid < 256) {
        // ================= fp32 / FFMA2 crew : rows bm+64 .. bm+127 ========
        float* Asf = (float*)smem;                    // [16][FP_AS_LD]
        float* Bsf = (float*)(smem + FP_AS_BYTES);    // [16][128]

        const int trow = tid >> 4;          // 0..15
        const int tcol = tid & 15;          // 0..15
        const int m0   = trow * 4;          // 0..60
        const int n0   = tcol * 4;

        const int lrow = tid >> 2;          // 0..63
        const int lkq  = (tid & 3) * 4;
        const int bkr  = tid >> 5;          // 0..7
        const int bc   = (tid & 31) * 4;

        const float* hPtr = H + (size_t)(bm + 64 + lrow) * (size_t)D + lkq;
        const float* wPtr = W + bkr * 128 + bc;

        unsigned long long acc[4][4];
#pragma unroll
        for (int i = 0; i < 4; i++)
#pragma unroll
            for (int j = 0; j < 4; j++) acc[i][j] = 0ull;

        const int nIter = D / 16;

        float4 ra  = *(const float4*)(hPtr);
        float4 rb0 = *(const float4*)(wPtr);
        float4 rb1 = *(const float4*)(wPtr + 8 * 128);

        for (int it = 0; it < nIter; ++it) {
            Asf[(lkq + 0) * FP_AS_LD + lrow] = ra.x;
            Asf[(lkq + 1) * FP_AS_LD + lrow] = ra.y;
            Asf[(lkq + 2) * FP_AS_LD + lrow] = ra.z;
            Asf[(lkq + 3) * FP_AS_LD + lrow] = ra.w;
            *(float4*)&Bsf[bkr * 128 + bc]       = rb0;
            *(float4*)&Bsf[(bkr + 8) * 128 + bc] = rb1;
            BARX(1);

            if (it + 1 < nIter) {
                ra  = *(const float4*)(hPtr + (size_t)(it + 1) * 16);
                const float* wp = wPtr + (size_t)(it + 1) * 16 * 128;
                rb0 = *(const float4*)(wp);
                rb1 = *(const float4*)(wp + 8 * 128);
            }

#pragma unroll
            for (int k = 0; k < 16; ++k) {
                float4 a4 = *(const float4*)&Asf[k * FP_AS_LD + m0];
                ulonglong2 lb0 = *(const ulonglong2*)&Bsf[k * 128 + n0];
                ulonglong2 lb1 = *(const ulonglong2*)&Bsf[k * 128 + n0 + 64];
                unsigned long long ap[4];
                ap[0] = pack_dup(a4.x); ap[1] = pack_dup(a4.y);
                ap[2] = pack_dup(a4.z); ap[3] = pack_dup(a4.w);
                unsigned long long bp[4] = { lb0.x, lb0.y, lb1.x, lb1.y };
#pragma unroll
                for (int mi = 0; mi < 4; ++mi)
#pragma unroll
                    for (int pj = 0; pj < 4; ++pj)
                        acc[mi][pj] = fma2(ap[mi], bp[pj], acc[mi][pj]);
            }
            BARX(1);
        }

        // writeback rows bm+64+m0+mi
#pragma unroll
        for (int mi = 0; mi < 4; ++mi) {
            const size_t m = (size_t)(bm + 64 + m0 + mi);
            ulonglong2 v0; v0.x = acc[mi][0]; v0.y = acc[mi][1];
            ulonglong2 v1; v1.x = acc[mi][2]; v1.y = acc[mi][3];
            *(ulonglong2*)&out[m * 128 + n0]      = v0;
            *(ulonglong2*)&out[m * 128 + n0 + 64] = v1;
        }
    } else {
        // ================= HMMA bf16x6 crew : rows bm .. bm+63 =============
        const int tid2 = tid - 256;
        const int wid2 = tid2 >> 5;         // 0..7
        const int wm   = (wid2 >> 2) * 32;  // 0 / 32
        const int wn   = (wid2 & 3) * 32;   // 0..96

        wmma::fragment<wmma::accumulator, 16, 16, 16, float> acc[2][2];
        float tot[2][2][8];
#pragma unroll
        for (int mi = 0; mi < 2; ++mi)
#pragma unroll
            for (int nj = 0; nj < 2; ++nj) {
                wmma::fill_fragment(acc[mi][nj], 0.0f);
#pragma unroll
                for (int i = 0; i < 8; ++i) tot[mi][nj][i] = 0.0f;
            }

        const int nch = D / 32;
        // A load mapping: row 0..63, 8 floats each
        const int arow = tid2 >> 2;
        const int aseg = (tid2 & 3) * 8;
        // B load mapping: e-row 0..127, 16 bf16 each
        const int erow = tid2 >> 1;
        const int ksg  = (tid2 & 1) * 16;

        float4 h4[2];
        uint4  wv[3][2];
        {
            const float4* hp = (const float4*)(H + (size_t)(bm + arow) * D + aseg);
            h4[0] = hp[0]; h4[1] = hp[1];
#pragma unroll
            for (int s = 0; s < 3; ++s) {
                const uint4* wp = (const uint4*)(g_Ws + (size_t)s * 128 * D
                                                 + (size_t)erow * D + ksg);
                wv[s][0] = wp[0]; wv[s][1] = wp[1];
            }
        }

        for (int c = 0; c < nch; ++c) {
            char* buf = smem + FP_BYTES + (c & 1) * HB_BUF;
            __nv_bfloat16* apl = (__nv_bfloat16*)buf;
            __nv_bfloat16* bpl = (__nv_bfloat16*)(buf + 3 * APL_B);

            // split H rows -> 3 A planes
            {
                float v[8] = { h4[0].x, h4[0].y, h4[0].z, h4[0].w,
                               h4[1].x, h4[1].y, h4[1].z, h4[1].w };
                uint32_t q0[4], q1[4], q2[4];
#pragma unroll
                for (int j = 0; j < 4; ++j) {
                    float x0 = v[2*j], x1 = v[2*j+1];
                    __nv_bfloat16 a0 = __float2bfloat16(x0);
                    __nv_bfloat16 c0 = __float2bfloat16(x1);
                    float r0 = x0 - __bfloat162float(a0);
                    float r1 = x1 - __bfloat162float(c0);
                    __nv_bfloat16 a1 = __float2bfloat16(r0);
                    __nv_bfloat16 c1 = __float2bfloat16(r1);
                    float t0 = r0 - __bfloat162float(a1);
                    float t1 = r1 - __bfloat162float(c1);
                    __nv_bfloat16 a2 = __float2bfloat16(t0);
                    __nv_bfloat16 c2 = __float2bfloat16(t1);
                    q0[j] = ((uint32_t)__bfloat16_as_ushort(c0) << 16) | __bfloat16_as_ushort(a0);
                    q1[j] = ((uint32_t)__bfloat16_as_ushort(c1) << 16) | __bfloat16_as_ushort(a1);
                    q2[j] = ((uint32_t)__bfloat16_as_ushort(c2) << 16) | __bfloat16_as_ushort(a2);
                }
                const int off = arow * LDP + aseg;
                *(uint4*)(apl + 0 * (64*LDP) + off) = make_uint4(q0[0], q0[1], q0[2], q0[3]);
                *(uint4*)(apl + 1 * (64*LDP) + off) = make_uint4(q1[0], q1[1], q1[2], q1[3]);
                *(uint4*)(apl + 2 * (64*LDP) + off) = make_uint4(q2[0], q2[1], q2[2], q2[3]);
            }
            // copy W planes
            {
                const int off = erow * LDP + ksg;
#pragma unroll
                for (int s = 0; s < 3; ++s) {
                    *(uint4*)(bpl + s * (128*LDP) + off)     = wv[s][0];
                    *(uint4*)(bpl + s * (128*LDP) + off + 8) = wv[s][1];
                }
            }
            BARX(2);

            if (c + 1 < nch) {
                const float4* hp = (const float4*)(H + (size_t)(bm + arow) * D
                                                   + (size_t)(c + 1) * 32 + aseg);
                h4[0] = hp[0]; h4[1] = hp[1];
#pragma unroll
                for (int s = 0; s < 3; ++s) {
                    const uint4* wp = (const uint4*)(g_Ws + (size_t)s * 128 * D
                                                     + (size_t)erow * D
                                                     + (size_t)(c + 1) * 32 + ksg);
                    wv[s][0] = wp[0]; wv[s][1] = wp[1];
                }
            }

#pragma unroll
            for (int ks = 0; ks < 2; ++ks) {
                const int k0 = ks * 16;
                wmma::fragment<wmma::matrix_b, 16, 16, 16, __nv_bfloat16, wmma::col_major> bfr[3][2];
#pragma unroll
                for (int s = 0; s < 3; ++s)
#pragma unroll
                    for (int nj = 0; nj < 2; ++nj)
                        wmma::load_matrix_sync(bfr[s][nj],
                            bpl + s * (128*LDP) + (wn + nj*16) * LDP + k0, LDP);

                wmma::fragment<wmma::matrix_a, 16, 16, 16, __nv_bfloat16, wmma::row_major> afr[2];

                // a0 : b0, b1, b2
#pragma unroll
                for (int mi = 0; mi < 2; ++mi)
                    wmma::load_matrix_sync(afr[mi],
                        apl + 0 * (64*LDP) + (wm + mi*16) * LDP + k0, LDP);
#pragma unroll
                for (int mi = 0; mi < 2; ++mi)
#pragma unroll
                    for (int nj = 0; nj < 2; ++nj) {
                        wmma::mma_sync(acc[mi][nj], afr[mi], bfr[0][nj], acc[mi][nj]);
                        wmma::mma_sync(acc[mi][nj], afr[mi], bfr[1][nj], acc[mi][nj]);
                        wmma::mma_sync(acc[mi][nj], afr[mi], bfr[2][nj], acc[mi][nj]);
                    }
                // a1 : b0, b1
#pragma unroll
                for (int mi = 0; mi < 2; ++mi)
                    wmma::load_matrix_sync(afr[mi],
                        apl + 1 * (64*LDP) + (wm + mi*16) * LDP + k0, LDP);
#pragma unroll
                for (int mi = 0; mi < 2; ++mi)
#pragma unroll
                    for (int nj = 0; nj < 2; ++nj) {
                        wmma::mma_sync(acc[mi][nj], afr[mi], bfr[0][nj], acc[mi][nj]);
                        wmma::mma_sync(acc[mi][nj], afr[mi], bfr[1][nj], acc[mi][nj]);
                    }
                // a2 : b0
#pragma unroll
                for (int mi = 0; mi < 2; ++mi)
                    wmma::load_matrix_sync(afr[mi],
                        apl + 2 * (64*LDP) + (wm + mi*16) * LDP + k0, LDP);
#pragma unroll
                for (int mi = 0; mi < 2; ++mi)
#pragma unroll
                    for (int nj = 0; nj < 2; ++nj)
                        wmma::mma_sync(acc[mi][nj], afr[mi], bfr[0][nj], acc[mi][nj]);
            }

            if ((c & (FLUSH_EVERY - 1)) == (FLUSH_EVERY - 1)) {
#pragma unroll
                for (int mi = 0; mi < 2; ++mi)
#pragma unroll
                    for (int nj = 0; nj < 2; ++nj)
#pragma unroll
                        for (int i = 0; i < 8; ++i) {
                            tot[mi][nj][i] += acc[mi][nj].x[i];
                            acc[mi][nj].x[i] = 0.0f;
                        }
            }
        }

#pragma unroll
        for (int mi = 0; mi < 2; ++mi)
#pragma unroll
            for (int nj = 0; nj < 2; ++nj) {
#pragma unroll
                for (int i = 0; i < 8; ++i)
                    acc[mi][nj].x[i] = tot[mi][nj][i] + acc[mi][nj].x[i];
                wmma::store_matrix_sync(out + (size_t)(bm + wm + mi*16) * 128 + wn + nj*16,
                                        acc[mi][nj], 128, wmma::mem_row_major);
            }
    }
}

// ===========================================================================
// Epilogue: one WARP per token (measured 26us)
// ===========================================================================
__global__ __launch_bounds__(128)
void router_epilogue(const float* __restrict__ logits,
                     const int* __restrict__ tmask,
                     float* __restrict__ out_mask,
                     float* __restrict__ out_probs,
                     float* __restrict__ out_lsel,
                     unsigned fk0, unsigned fk1)
{
    const int lane = threadIdx.x & 31;
    const int t    = blockIdx.x * 4 + (threadIdx.x >> 5);
    const unsigned base = (unsigned)t * 128u + (unsigned)lane * 4u;

    const float4 l4 = *(const float4*)&logits[base];
    float lc[4] = { l4.x, l4.y, l4.z, l4.w };
    const bool tm = (tmask[t] != 0);

    float lsm[4];
#pragma unroll
    for (int j = 0; j < 4; ++j) {
        unsigned o0, o1;
        threefry2x32(fk0, fk1, 0u, base + (unsigned)j, o0, o1);
        const unsigned bits = o0 ^ o1;
        float f = __uint_as_float((bits >> 9) | 0x3f800000u) - 1.0f;
        const float minv = 1e-6f;
        const float maxv = (float)(1.0 - 1e-6);
        float u = fmaxf(minv, f * (maxv - minv) + minv);
        const float g = -logf(-logf(u));
        lsm[j] = tm ? (lc[j] + g) : -INFINITY;
    }

    float v[4] = { lsm[0], lsm[1], lsm[2], lsm[3] };
    bool sel[4] = { false, false, false, false };
#pragma unroll 1
    for (int it = 0; it < 8; ++it) {
        float bv = v[0];
        int   bg = lane * 4;
#pragma unroll
        for (int j = 1; j < 4; ++j)
            if (v[j] > bv) { bv = v[j]; bg = lane * 4 + j; }
#pragma unroll
        for (int off = 16; off; off >>= 1) {
            float ov = __shfl_xor_sync(0xffffffffu, bv, off);
            int   og = __shfl_xor_sync(0xffffffffu, bg, off);
            if (ov > bv || (ov == bv && og < bg)) { bv = ov; bg = og; }
        }
#pragma unroll
        for (int j = 0; j < 4; ++j)
            if (bg == lane * 4 + j) { sel[j] = true; v[j] = -INFINITY; }
    }

    float mx = fmaxf(fmaxf(lc[0], lc[1]), fmaxf(lc[2], lc[3]));
#pragma unroll
    for (int off = 16; off; off >>= 1)
        mx = fmaxf(mx, __shfl_xor_sync(0xffffffffu, mx, off));

    float ex[4];
    float s = 0.0f;
#pragma unroll
    for (int j = 0; j < 4; ++j) { ex[j] = expf(lc[j] - mx); s += ex[j]; }
#pragma unroll
    for (int off = 16; off; off >>= 1)
        s += __shfl_xor_sync(0xffffffffu, s, off);

    float p[4];
#pragma unroll
    for (int j = 0; j < 4; ++j) p[j] = tm ? (ex[j] / s) : 0.0f;

    float ms = 0.0f;
#pragma unroll
    for (int j = 0; j < 4; ++j) if (sel[j]) ms += p[j];
#pragma unroll
    for (int off = 16; off; off >>= 1)
        ms += __shfl_xor_sync(0xffffffffu, ms, off);
    const float den = fmaxf(ms, 1e-9f);

    float4 omask, oprob, osel;
    float* om = &omask.x; float* op = &oprob.x; float* os = &osel.x;
#pragma unroll
    for (int j = 0; j < 4; ++j) {
        float pr = sel[j] ? (p[j] / den) : 0.0f;
        om[j] = (sel[j] && tm) ? 1.0f : 0.0f;
        op[j] = tm ? pr : 0.0f;
        os[j] = lsm[j];
    }
    *(float4*)&out_mask [base] = omask;
    *(float4*)&out_probs[base] = oprob;
    *(float4*)&out_lsel [base] = osel;
}

// ===========================================================================
// launch
// ===========================================================================
extern "C" void kernel_launch(void* const* d_in, const int* in_sizes, int n_in,
                              void* d_out, int out_size)
{
    const float* H  = (const float*)d_in[0];
    const float* W  = (const float*)d_in[1];
    const int*   tm = (const int*)d_in[2];

    const int T = in_sizes[2];                 // 16384
    const int D = in_sizes[0] / T;             // 4096

    float* outF      = (float*)d_out;
    const unsigned TE = (unsigned)T * 128u;
    float* out_mask  = outF;
    float* out_probs = outF + TE;
    float* out_clean = outF + 2u * TE;
    float* out_sel   = outF + 3u * TE;

    cudaFuncSetAttribute(gemm_hybrid, cudaFuncAttributeMaxDynamicSharedMemorySize,
                         SMEM_TOTAL);

    wsplit_kernel<<<dim3(D / 32, 4), dim3(32, 8)>>>(W, D);
    gemm_hybrid<<<T / 128, 512, SMEM_TOTAL>>>(H, W, out_clean, D);

    unsigned fk0, fk1;
    threefry2x32(0u, 7u, 0u, 1u, fk0, fk1);

    router_epilogue<<<T / 4, 128>>>(out_clean, tm, out_mask, out_probs, out_sel,
                                    fk0, fk1);
}

// round 11
// speedup vs baseline: 1.8933x; 1.8933x over previous
#include <cuda_runtime.h>
#include <cstdint>
#include <math.h>

// ---------------------------------------------------------------------------
// Threefry-2x32 (exact JAX implementation: jax/_src/prng.py)
// ---------------------------------------------------------------------------
__host__ __device__ __forceinline__ void threefry2x32(
    unsigned k0, unsigned k1, unsigned x0, unsigned x1,
    unsigned &o0, unsigned &o1)
{
    const unsigned ks2 = k0 ^ k1 ^ 0x1BD11BDAu;
    unsigned a = x0 + k0, b = x1 + k1;
#define TF_ROT(v,d) (((v)<<(d))|((v)>>(32-(d))))
#define TF_R4(r0_,r1_,r2_,r3_) \
    a+=b; b=TF_ROT(b,r0_); b^=a; \
    a+=b; b=TF_ROT(b,r1_); b^=a; \
    a+=b; b=TF_ROT(b,r2_); b^=a; \
    a+=b; b=TF_ROT(b,r3_); b^=a;
    TF_R4(13,15,26, 6);  a+=k1;  b+=ks2+1u;
    TF_R4(17,29,16,24);  a+=ks2; b+=k0 +2u;
    TF_R4(13,15,26, 6);  a+=k0;  b+=k1 +3u;
    TF_R4(17,29,16,24);  a+=k1;  b+=ks2+4u;
    TF_R4(13,15,26, 6);  a+=ks2; b+=k0 +5u;
    o0 = a; o1 = b;
#undef TF_R4
#undef TF_ROT
}

// ---------------------------------------------------------------------------
// Packed fp32x2 helpers (sm_103a FFMA2 — 2x FFMA throughput)
// ---------------------------------------------------------------------------
__device__ __forceinline__ unsigned long long pack_dup(float a) {
    unsigned long long r;
    asm("mov.b64 %0, {%1, %1};" : "=l"(r) : "f"(a));
    return r;
}
__device__ __forceinline__ unsigned long long fma2(
    unsigned long long a, unsigned long long b, unsigned long long c) {
    unsigned long long d;
    asm("fma.rn.f32x2 %0, %1, %2, %3;" : "=l"(d) : "l"(a), "l"(b), "l"(c));
    return d;
}

// ---------------------------------------------------------------------------
// GEMM: out[T,128] = H[T,D] @ W[D,128], fp32 accurate.  (R4, measured 377us)
// Tile 128x128xBK16, 256 threads, 8x8 micro-tiles, FFMA2 over expert pairs.
// ---------------------------------------------------------------------------
__global__ __launch_bounds__(256, 1)
void gemm128(const float* __restrict__ H, const float* __restrict__ W,
             float* __restrict__ out, int D)
{
    __shared__ float As[16][132];   // transposed h tile (padded rows)
    __shared__ float Bs[16][128];

    const int tid = threadIdx.x;
    const int bm  = blockIdx.x * 128;

    // compute-thread mapping: 16x16 grid, 4+4 split in each dim
    const int trow = tid >> 4;          // 0..15
    const int tcol = tid & 15;          // 0..15
    const int m0   = trow * 4;
    const int n0   = tcol * 4;

    // load mapping
    const int lrow = tid >> 2;          // 0..63 (A rows; +64 for second half)
    const int lkq  = (tid & 3) * 4;     // k offset within BK
    const int bkr  = tid >> 5;          // 0..7  (B k rows; +8 second half)
    const int bc   = (tid & 31) * 4;    // B column

    const float* hPtr = H + (size_t)(bm + lrow) * (size_t)D + lkq;
    const float* wPtr = W + bkr * 128 + bc;

    unsigned long long acc[8][4];
#pragma unroll
    for (int i = 0; i < 8; i++)
#pragma unroll
        for (int j = 0; j < 4; j++) acc[i][j] = 0ull;

    const int nIter = D / 16;

    // preload tile 0
    float4 ra0 = *(const float4*)(hPtr);
    float4 ra1 = *(const float4*)(hPtr + (size_t)64 * D);
    float4 rb0 = *(const float4*)(wPtr);
    float4 rb1 = *(const float4*)(wPtr + 8 * 128);

    for (int it = 0; it < nIter; ++it) {
        // store current tile to smem (A transposed)
        As[lkq + 0][lrow]      = ra0.x;
        As[lkq + 1][lrow]      = ra0.y;
        As[lkq + 2][lrow]      = ra0.z;
        As[lkq + 3][lrow]      = ra0.w;
        As[lkq + 0][lrow + 64] = ra1.x;
        As[lkq + 1][lrow + 64] = ra1.y;
        As[lkq + 2][lrow + 64] = ra1.z;
        As[lkq + 3][lrow + 64] = ra1.w;
        *(float4*)&Bs[bkr    ][bc] = rb0;
        *(float4*)&Bs[bkr + 8][bc] = rb1;
        __syncthreads();

        // prefetch next tile into registers (hidden under compute)
        if (it + 1 < nIter) {
            const float* hp = hPtr + (size_t)(it + 1) * 16;
            ra0 = *(const float4*)(hp);
            ra1 = *(const float4*)(hp + (size_t)64 * D);
            const float* wp = wPtr + (size_t)(it + 1) * 16 * 128;
            rb0 = *(const float4*)(wp);
            rb1 = *(const float4*)(wp + 8 * 128);
        }

#pragma unroll
        for (int k = 0; k < 16; ++k) {
            float4 a0 = *(const float4*)&As[k][m0];
            float4 a1 = *(const float4*)&As[k][m0 + 64];
            unsigned long long bp[4];
            bp[0] = *(const unsigned long long*)&Bs[k][n0];
            bp[1] = *(const unsigned long long*)&Bs[k][n0 + 2];
            bp[2] = *(const unsigned long long*)&Bs[k][n0 + 64];
            bp[3] = *(const unsigned long long*)&Bs[k][n0 + 66];
            unsigned long long ap[8];
            ap[0] = pack_dup(a0.x); ap[1] = pack_dup(a0.y);
            ap[2] = pack_dup(a0.z); ap[3] = pack_dup(a0.w);
            ap[4] = pack_dup(a1.x); ap[5] = pack_dup(a1.y);
            ap[6] = pack_dup(a1.z); ap[7] = pack_dup(a1.w);
#pragma unroll
            for (int mi = 0; mi < 8; ++mi)
#pragma unroll
                for (int pj = 0; pj < 4; ++pj)
                    acc[mi][pj] = fma2(ap[mi], bp[pj], acc[mi][pj]);
        }
        __syncthreads();
    }

    // writeback (8B stores of fp32 pairs; n even -> aligned)
#pragma unroll
    for (int mi = 0; mi < 8; ++mi) {
        const int m = bm + m0 + (mi & 3) + ((mi >> 2) << 6);
#pragma unroll
        for (int pj = 0; pj < 4; ++pj) {
            const int n = n0 + ((pj & 1) << 1) + ((pj >> 1) << 6);
            *(unsigned long long*)&out[(size_t)m * 128 + n] = acc[mi][pj];
        }
    }
}

// ---------------------------------------------------------------------------
// Epilogue: one WARP per token (R5, measured 26us).
// Each lane owns 4 experts. No __syncthreads, no smem: butterfly reductions.
// ---------------------------------------------------------------------------
__global__ __launch_bounds__(128)
void router_epilogue(const float* __restrict__ logits,
                     const int* __restrict__ tmask,   // 4-byte bool
                     float* __restrict__ out_mask,
                     float* __restrict__ out_probs,
                     float* __restrict__ out_lsel,
                     unsigned fk0, unsigned fk1)
{
    const int lane = threadIdx.x & 31;
    const int t    = blockIdx.x * 4 + (threadIdx.x >> 5);
    const unsigned base = (unsigned)t * 128u + (unsigned)lane * 4u;

    const float4 l4 = *(const float4*)&logits[base];
    float lc[4] = { l4.x, l4.y, l4.z, l4.w };
    const bool tm = (tmask[t] != 0);

    // --- JAX-exact gumbel (jax_threefry_partitionable=True): bits = o0^o1 ---
    float lsm[4];
#pragma unroll
    for (int j = 0; j < 4; ++j) {
        unsigned o0, o1;
        threefry2x32(fk0, fk1, 0u, base + (unsigned)j, o0, o1);
        const unsigned bits = o0 ^ o1;
        float f = __uint_as_float((bits >> 9) | 0x3f800000u) - 1.0f;
        const float minv = 1e-6f;
        const float maxv = (float)(1.0 - 1e-6);
        float u = fmaxf(minv, f * (maxv - minv) + minv);
        const float g = -logf(-logf(u));
        lsm[j] = tm ? (lc[j] + g) : -INFINITY;
    }

    // --- top-8: iterative warp argmax (ties -> lowest global index) --------
    float v[4] = { lsm[0], lsm[1], lsm[2], lsm[3] };
    bool sel[4] = { false, false, false, false };
#pragma unroll 1
    for (int it = 0; it < 8; ++it) {
        float bv = v[0];
        int   bg = lane * 4;
#pragma unroll
        for (int j = 1; j < 4; ++j)
            if (v[j] > bv) { bv = v[j]; bg = lane * 4 + j; }
#pragma unroll
        for (int off = 16; off; off >>= 1) {
            float ov = __shfl_xor_sync(0xffffffffu, bv, off);
            int   og = __shfl_xor_sync(0xffffffffu, bg, off);
            if (ov > bv || (ov == bv && og < bg)) { bv = ov; bg = og; }
        }
#pragma unroll
        for (int j = 0; j < 4; ++j)
            if (bg == lane * 4 + j) { sel[j] = true; v[j] = -INFINITY; }
    }

    // --- softmax over clean logits ----------------------------------------
    float mx = fmaxf(fmaxf(lc[0], lc[1]), fmaxf(lc[2], lc[3]));
#pragma unroll
    for (int off = 16; off; off >>= 1)
        mx = fmaxf(mx, __shfl_xor_sync(0xffffffffu, mx, off));

    float ex[4];
    float s = 0.0f;
#pragma unroll
    for (int j = 0; j < 4; ++j) { ex[j] = expf(lc[j] - mx); s += ex[j]; }
#pragma unroll
    for (int off = 16; off; off >>= 1)
        s += __shfl_xor_sync(0xffffffffu, s, off);

    float p[4];
#pragma unroll
    for (int j = 0; j < 4; ++j) p[j] = tm ? (ex[j] / s) : 0.0f;

    // --- masked renorm -----------------------------------------------------
    float ms = 0.0f;
#pragma unroll
    for (int j = 0; j < 4; ++j) if (sel[j]) ms += p[j];
#pragma unroll
    for (int off = 16; off; off >>= 1)
        ms += __shfl_xor_sync(0xffffffffu, ms, off);
    const float den = fmaxf(ms, 1e-9f);

    float4 omask, oprob, osel;
    float* om = &omask.x; float* op = &oprob.x; float* os = &osel.x;
#pragma unroll
    for (int j = 0; j < 4; ++j) {
        float pr = sel[j] ? (p[j] / den) : 0.0f;
        om[j] = (sel[j] && tm) ? 1.0f : 0.0f;
        op[j] = tm ? pr : 0.0f;
        os[j] = lsm[j];
    }
    *(float4*)&out_mask [base] = omask;
    *(float4*)&out_probs[base] = oprob;
    *(float4*)&out_lsel [base] = osel;
}

// ---------------------------------------------------------------------------
// launch
// ---------------------------------------------------------------------------
extern "C" void kernel_launch(void* const* d_in, const int* in_sizes, int n_in,
                              void* d_out, int out_size)
{
    const float* H  = (const float*)d_in[0];
    const float* W  = (const float*)d_in[1];
    const int*   tm = (const int*)d_in[2];     // bool promoted to 4-byte

    const int T = in_sizes[2];                 // 16384
    const int D = in_sizes[0] / T;             // 4096

    float* outF      = (float*)d_out;
    const unsigned TE = (unsigned)T * 128u;
    float* out_mask  = outF;
    float* out_probs = outF + TE;
    float* out_clean = outF + 2u * TE;
    float* out_sel   = outF + 3u * TE;

    gemm128<<<T / 128, 256>>>(H, W, out_clean, D);

    // folded key: fold_in(key(7), 1) = threefry([0,7], [0,1])
    unsigned fk0, fk1;
    threefry2x32(0u, 7u, 0u, 1u, fk0, fk1);

    router_epilogue<<<T / 4, 128>>>(out_clean, tm, out_mask, out_probs, out_sel,
                                    fk0, fk1);
}